// round 1
// baseline (speedup 1.0000x reference)
#include <cuda_runtime.h>
#include <cstdint>

#define B_TOTAL   262144
#define NE        128
#define RR        256
#define RANK      16
#define THREADS   512
#define ROWS_PER_TILE 32
#define NTILES    (B_TOTAL / ROWS_PER_TILE)   // 8192
#define OSTRIDE   132                          // padded occ row stride (floats)
#define JSTRIDE   260                          // padded j matrix stride (floats)
#define W_FLOATS  (NE * RR)                    // 32768
#define OBUF_FLOATS (ROWS_PER_TILE * OSTRIDE)  // 4224
#define J_FLOATS  (ROWS_PER_TILE * JSTRIDE)    // 8320
#define SMEM_FLOATS (W_FLOATS + 2 * OBUF_FLOATS + J_FLOATS)  // 49536 floats = 198144 B

__device__ __forceinline__ void cp_async16(void* dst_smem, const void* src) {
    unsigned d = (unsigned)__cvta_generic_to_shared(dst_smem);
    asm volatile("cp.async.ca.shared.global [%0], [%1], 16;" :: "r"(d), "l"(src) : "memory");
}
__device__ __forceinline__ void cp_commit() {
    asm volatile("cp.async.commit_group;" ::: "memory");
}
__device__ __forceinline__ void cp_wait1() {
    asm volatile("cp.async.wait_group 1;" ::: "memory");
}

__global__ void __launch_bounds__(THREADS, 1)
jastrow_slogdet_kernel(const float* __restrict__ occ,
                       const float* __restrict__ Wg,
                       const float* __restrict__ bvec,
                       float* __restrict__ out)
{
    extern __shared__ float smem[];
    float* Wsh = smem;                               // [128][256]
    float* Osh = smem + W_FLOATS;                    // 2 x [32][OSTRIDE]
    float* Jsh = smem + W_FLOATS + 2 * OBUF_FLOATS;  // [32][JSTRIDE]

    const int tid  = threadIdx.x;
    const int warp = tid >> 5;
    const int lane = tid & 31;
    const int g    = lane >> 4;       // sub-group 0/1 within warp
    const int li   = lane & 15;       // lane within 16-group == matrix row index
    const int m    = warp * 2 + g;    // matrix slot in tile, 0..31
    const unsigned hmask = (lane < 16) ? 0x0000FFFFu : 0xFFFF0000u;

    // ---- Load W into SMEM (once per CTA, stays resident) ----
    {
        const float4* W4  = (const float4*)Wg;
        float4*       Ws4 = (float4*)Wsh;
        #pragma unroll
        for (int i = 0; i < W_FLOATS / 4 / THREADS; i++)   // 16 iters
            Ws4[tid + i * THREADS] = W4[tid + i * THREADS];
    }

    // ---- b values for this lane's 16 output columns ----
    float4 bb[4];
    #pragma unroll
    for (int i = 0; i < 4; i++)
        bb[i] = ((const float4*)bvec)[i * 16 + li];

    // ---- Prefetch first occ tile ----
    int t0 = (int)blockIdx.x;
    int buf = 0;
    if (t0 < NTILES) {
        const float4* src = (const float4*)(occ + (size_t)t0 * ROWS_PER_TILE * NE);
        #pragma unroll
        for (int i = 0; i < 2; i++) {
            int idx = tid + i * THREADS;         // 0..1023 float4s
            int r = idx >> 5, c = idx & 31;      // 32 float4 per row
            cp_async16(Osh + r * OSTRIDE + c * 4, src + idx);
        }
    }
    cp_commit();

    for (int t = t0; t < NTILES; t += (int)gridDim.x) {
        // ---- prefetch next tile into other buffer ----
        int tn = t + (int)gridDim.x;
        int nbuf = buf ^ 1;
        if (tn < NTILES) {
            const float4* src = (const float4*)(occ + (size_t)tn * ROWS_PER_TILE * NE);
            #pragma unroll
            for (int i = 0; i < 2; i++) {
                int idx = tid + i * THREADS;
                int r = idx >> 5, c = idx & 31;
                cp_async16(Osh + nbuf * OBUF_FLOATS + r * OSTRIDE + c * 4, src + idx);
            }
        }
        cp_commit();
        cp_wait1();           // current buf's data has landed
        __syncthreads();

        // ======== GEMM: this 16-lane group computes one full batch row ========
        // lane li owns output columns c = i*64 + li*4 + q  (i,q in 0..3)
        const float* orow = Osh + buf * OBUF_FLOATS + m * OSTRIDE;
        float acc[16];
        #pragma unroll
        for (int i = 0; i < 4; i++) {
            acc[i*4+0] = bb[i].x; acc[i*4+1] = bb[i].y;
            acc[i*4+2] = bb[i].z; acc[i*4+3] = bb[i].w;
        }

        #pragma unroll 2
        for (int k4 = 0; k4 < NE / 4; k4++) {
            float4 o = ((const float4*)orow)[k4];    // broadcast within group
            float ok[4] = {o.x, o.y, o.z, o.w};
            #pragma unroll
            for (int kk = 0; kk < 4; kk++) {
                const float4* wrow = (const float4*)(Wsh + (k4 * 4 + kk) * RR);
                float ov = ok[kk];
                #pragma unroll
                for (int i = 0; i < 4; i++) {
                    float4 w = wrow[i * 16 + li];    // coalesced, conflict-free
                    acc[i*4+0] += ov * w.x;
                    acc[i*4+1] += ov * w.y;
                    acc[i*4+2] += ov * w.z;
                    acc[i*4+3] += ov * w.w;
                }
            }
        }

        // ======== Stage through SMEM to get "lane = matrix row" layout ========
        float* jrow = Jsh + m * JSTRIDE;
        #pragma unroll
        for (int i = 0; i < 4; i++) {
            float4 v;
            v.x = acc[i*4+0]; v.y = acc[i*4+1]; v.z = acc[i*4+2]; v.w = acc[i*4+3];
            *(float4*)(jrow + i * 64 + li * 4) = v;
        }
        __syncwarp();
        float a[RANK];
        #pragma unroll
        for (int i = 0; i < 4; i++) {
            float4 v = *(const float4*)(jrow + li * 16 + i * 4);
            a[i*4+0] = v.x; a[i*4+1] = v.y; a[i*4+2] = v.z; a[i*4+3] = v.w;
        }
        // I + j
        #pragma unroll
        for (int j = 0; j < RANK; j++)
            a[j] += (j == li) ? 1.0f : 0.0f;

        // ======== LU with partial pivoting, registers + width-16 shuffles ========
        float sign = 1.0f, logabs = 0.0f;
        #pragma unroll
        for (int k = 0; k < RANK; k++) {
            // argmax |a[i][k]| over rows i >= k (lowest index wins ties)
            float v = (li >= k) ? fabsf(a[k]) : -1.0f;
            int idx = li;
            #pragma unroll
            for (int off = 8; off >= 1; off >>= 1) {
                float ov = __shfl_xor_sync(hmask, v, off, 16);
                int   oi = __shfl_xor_sync(hmask, idx, off, 16);
                bool take = (ov > v) || (ov == v && oi < idx);
                v   = take ? ov : v;
                idx = take ? oi : idx;
            }
            const int p = idx;                 // uniform within 16-group
            if (p != k) sign = -sign;

            // swap rows k and p (only columns >= k matter)
            int srcl = (li == k) ? p : ((li == p) ? k : li);
            #pragma unroll
            for (int j = 0; j < RANK; j++) {
                if (j >= k)
                    a[j] = __shfl_sync(hmask, a[j], srcl, 16);
            }
            float piv = __shfl_sync(hmask, a[k], k, 16);
            if (piv < 0.0f) sign = -sign;
            logabs += __logf(fabsf(piv));

            float f = (li > k) ? __fdividef(a[k], piv) : 0.0f;
            #pragma unroll
            for (int j = 0; j < RANK; j++) {
                if (j >= k + 1) {
                    float prj = __shfl_sync(hmask, a[j], k, 16);
                    a[j] -= f * prj;
                }
            }
        }

        if (li == 0) {
            int gr = t * ROWS_PER_TILE + m;
            out[gr]           = sign;
            out[B_TOTAL + gr] = logabs;
        }
        __syncthreads();    // all done with buf before iter+2 overwrites it
        buf ^= 1;
    }
}

extern "C" void kernel_launch(void* const* d_in, const int* in_sizes, int n_in,
                              void* d_out, int out_size) {
    const float* occ = (const float*)d_in[0];
    const float* Wg  = (const float*)d_in[1];
    const float* bv  = (const float*)d_in[2];
    float* out = (float*)d_out;

    int dev = 0;
    cudaGetDevice(&dev);
    int sms = 148;
    cudaDeviceGetAttribute(&sms, cudaDevAttrMultiProcessorCount, dev);
    int grid = sms * 2;   // persistent-ish: ~2 waves at 1 CTA/SM, grid-stride over tiles

    size_t smem_bytes = SMEM_FLOATS * sizeof(float);   // 198144 B
    cudaFuncSetAttribute(jastrow_slogdet_kernel,
                         cudaFuncAttributeMaxDynamicSharedMemorySize,
                         (int)smem_bytes);

    jastrow_slogdet_kernel<<<grid, THREADS, smem_bytes>>>(occ, Wg, bv, out);
}